// round 6
// baseline (speedup 1.0000x reference)
#include <cuda_runtime.h>
#include <math.h>

#define T_   1024
#define B_   32
#define IN_  1024
#define H_   512
#define TB_  (T_ * B_)

typedef unsigned long long ull;

// ---------------- static device scratch (no runtime alloc allowed) ----------
__device__ float    g_xin[2][(size_t)TB_ * H_];   // per-direction input projections (biases folded)
__device__ float    g_seq[(size_t)TB_ * 2 * H_];  // layer-0 output, [t][b][2H]
__device__ float    g_hex[4][B_ * H_];            // h*noise_h exchange: [dir*2+buf][b][h]
__device__ unsigned g_ctr[32];                    // barriers: [layer][dir][batch-group]

// ---------------- f32x2 helpers (ptxas never emits FFMA2 from C++) ----------
__device__ __forceinline__ ull pk2(float lo, float hi) {
    ull r; asm("mov.b64 %0, {%1,%2};" : "=l"(r) : "f"(lo), "f"(hi)); return r;
}
__device__ __forceinline__ void upk2(ull v, float& lo, float& hi) {
    asm("mov.b64 {%0,%1}, %2;" : "=f"(lo), "=f"(hi) : "l"(v));
}
__device__ __forceinline__ void fma2(ull& d, ull a, ull b) {
    asm("fma.rn.f32x2 %0, %1, %2, %0;" : "+l"(d) : "l"(a), "l"(b));
}

// ---------------- init: zero barrier counters every launch (graph replay) ---
__global__ void init_kernel() {
    if (threadIdx.x < 32) g_ctr[threadIdx.x] = 0u;
}

// ---------------------------------------------------------------------------
// Input-projection GEMM:
//   g_xin[cell][m][n] = sum_k A[m][k] * noise_in[c][b][k] * w_ih[c][n][k]
//                       + b_ih[c][n] + b_hh[c][n],     m = t*B + b
// Layer 0: A = x ([B,T,IN] batch-first). Layer 1: A = g_seq ([m][1024]).
// Tile BM=128, BN=64, BK=16; 256 threads; 8m x 4n per thread via f32x2.
// ---------------------------------------------------------------------------
__global__ __launch_bounds__(256, 2) void gemm_kernel(
    const float* __restrict__ x,
    const float* __restrict__ w_ih,
    const float* __restrict__ b_ih,
    const float* __restrict__ b_hh,
    const float* __restrict__ noise_in,
    int layer)
{
    __shared__ float As[16 * 132];   // [k][m], padded (528 B row stride, 16B-aligned)
    __shared__ float Bs[16 * 68];    // [k][n], padded (272 B row stride, 16B-aligned)

    const int tid  = threadIdx.x;
    const int cell = blockIdx.z;                 // direction within layer
    const int cabs = layer * 2 + cell;           // absolute cell index
    const int n0   = blockIdx.x * 64;
    const int m0   = blockIdx.y * 128;
    const int tx   = tid & 15;
    const int ty   = tid >> 4;
    const int msub = ty * 8;
    const int nsub = tx * 4;

    const float* A  = (layer == 0) ? x : g_seq;
    const float* nz = noise_in + (size_t)cabs * B_ * IN_;
    const float* wb = w_ih + (size_t)cabs * H_ * IN_;
    float* outp = g_xin[cell];

    ull acc[4][4];
#pragma unroll
    for (int i = 0; i < 4; i++)
#pragma unroll
        for (int j = 0; j < 4; j++) acc[i][j] = 0ull;

    // A loader: 512 float4 per tile, 2 per thread
    const int e0 = tid, e1 = tid + 256;
    const int row0 = e0 >> 2, kq0 = (e0 & 3) * 4;
    const int row1 = e1 >> 2, kq1 = (e1 & 3) * 4;
    size_t ab0, ab1;
    if (layer == 0) {   // m = t*B + b ; x addr = b*(T*IN) + t*IN
        ab0 = (size_t)(row0 & 31) * ((size_t)T_ * IN_) + (size_t)(m0 / 32 + (row0 >> 5)) * IN_;
        ab1 = (size_t)(row1 & 31) * ((size_t)T_ * IN_) + (size_t)(m0 / 32 + (row1 >> 5)) * IN_;
    } else {
        ab0 = (size_t)(m0 + row0) * IN_;
        ab1 = (size_t)(m0 + row1) * IN_;
    }
    const size_t nb0 = (size_t)(row0 & 31) * IN_;
    const size_t nb1 = (size_t)(row1 & 31) * IN_;
    // B loader: 256 float4, 1 per thread
    const int brow = tid >> 2, bkq = (tid & 3) * 4;
    const float* wrow = wb + (size_t)(n0 + brow) * IN_ + bkq;

    for (int k0 = 0; k0 < IN_; k0 += 16) {
        __syncthreads();
        {
            float4 xv = *(const float4*)(A + ab0 + k0 + kq0);
            float4 nv = *(const float4*)(nz + nb0 + k0 + kq0);
            As[(kq0 + 0) * 132 + row0] = xv.x * nv.x;
            As[(kq0 + 1) * 132 + row0] = xv.y * nv.y;
            As[(kq0 + 2) * 132 + row0] = xv.z * nv.z;
            As[(kq0 + 3) * 132 + row0] = xv.w * nv.w;
            xv = *(const float4*)(A + ab1 + k0 + kq1);
            nv = *(const float4*)(nz + nb1 + k0 + kq1);
            As[(kq1 + 0) * 132 + row1] = xv.x * nv.x;
            As[(kq1 + 1) * 132 + row1] = xv.y * nv.y;
            As[(kq1 + 2) * 132 + row1] = xv.z * nv.z;
            As[(kq1 + 3) * 132 + row1] = xv.w * nv.w;
        }
        {
            float4 wv = *(const float4*)(wrow + k0);
            Bs[(bkq + 0) * 68 + brow] = wv.x;
            Bs[(bkq + 1) * 68 + brow] = wv.y;
            Bs[(bkq + 2) * 68 + brow] = wv.z;
            Bs[(bkq + 3) * 68 + brow] = wv.w;
        }
        __syncthreads();
#pragma unroll
        for (int k = 0; k < 16; k++) {
            float4 b4 = *(const float4*)&Bs[k * 68 + nsub];
            ull bd0 = pk2(b4.x, b4.x);
            ull bd1 = pk2(b4.y, b4.y);
            ull bd2 = pk2(b4.z, b4.z);
            ull bd3 = pk2(b4.w, b4.w);
#pragma unroll
            for (int mp = 0; mp < 4; mp++) {
                ull au = *(const ull*)&As[k * 132 + msub + 2 * mp];  // aligned m-pair
                fma2(acc[mp][0], au, bd0);
                fma2(acc[mp][1], au, bd1);
                fma2(acc[mp][2], au, bd2);
                fma2(acc[mp][3], au, bd3);
            }
        }
    }

    // Epilogue: fold b_ih + b_hh, write xin
    float bi[4];
#pragma unroll
    for (int nn = 0; nn < 4; nn++) {
        int n = n0 + nsub + nn;
        bi[nn] = b_ih[cabs * H_ + n] + b_hh[cabs * H_ + n];
    }
#pragma unroll
    for (int mp = 0; mp < 4; mp++) {
        float lo[4], hi[4];
#pragma unroll
        for (int nn = 0; nn < 4; nn++) upk2(acc[mp][nn], lo[nn], hi[nn]);
        float4 v0 = make_float4(lo[0] + bi[0], lo[1] + bi[1], lo[2] + bi[2], lo[3] + bi[3]);
        float4 v1 = make_float4(hi[0] + bi[0], hi[1] + bi[1], hi[2] + bi[2], hi[3] + bi[3]);
        size_t r0 = (size_t)(m0 + msub + 2 * mp) * H_ + n0 + nsub;
        *(float4*)(outp + r0)      = v0;
        *(float4*)(outp + r0 + H_) = v1;
    }
}

// ---------------------------------------------------------------------------
// Recurrent scan. 128 persistent CTAs: blockIdx>>6 = direction, 64 CTAs each.
// CTA owns 4 batches x 64 h-columns; W_hh slice in registers (f32x2 pairs).
// h*noise_h exchanged via double-buffered global buffer (.cg loads) with a
// per-(dir,batch-group) 8-CTA acquire/release barrier each step.
// ---------------------------------------------------------------------------
__global__ __launch_bounds__(256, 1) void recur_kernel(
    const float* __restrict__ w_hh,
    const float* __restrict__ noise_h,
    const float* __restrict__ mask,
    float* __restrict__ out,      // d_out: [B,T,2H] (layer 1 writes here)
    float* __restrict__ hn,       // d_out + B*T*2H: [L*D,B,H]
    int layer)
{
    __shared__ float4 hs4[512];   // staged h*nh: [local_b][k/4]
    __shared__ float4 red[256];   // split-K reduction

    const int tid = threadIdx.x;
    const int dir = blockIdx.x >> 6;
    const int id  = blockIdx.x & 63;
    const int b0  = (id >> 3) * 4;          // batch group of 4
    const int h0  = (id & 7) * 64;          // h-slice
    const int kp  = tid >> 6;               // warp-uniform K partition (0..3)
    const int hl  = tid & 63;
    const int h   = h0 + hl;
    const int c   = layer * 2 + dir;
    unsigned* ctr = &g_ctr[layer * 16 + dir * 8 + (id >> 3)];

    // W_hh slice into registers as aligned f32x2 pairs: w[h][kp*128 .. +127]
    union F4U2 { float4 f; ulonglong2 u; };
    ulonglong2 wu[32];
    {
        const float4* wp = (const float4*)(w_hh + ((size_t)c * H_ + h) * H_ + kp * 128);
#pragma unroll
        for (int i = 0; i < 32; i++) { F4U2 t; t.f = wp[i]; wu[i] = t.u; }
    }

    const bool epi = (tid < 64);            // kp==0 threads own the epilogue
    float nh[4], hprev[4];
    if (epi) {
#pragma unroll
        for (int b = 0; b < 4; b++) {
            nh[b]    = noise_h[((size_t)c * B_ + b0 + b) * H_ + h];
            hprev[b] = 0.0f;
        }
    }
    const float* xin = g_xin[dir];

    for (int t = 0; t < T_; t++) {
        const int ta = dir ? (T_ - 1 - t) : t;

        // prefetch xin + mask for this step (independent of the barrier)
        float xv[4], mt[4];
        if (epi) {
#pragma unroll
            for (int b = 0; b < 4; b++) {
                xv[b] = __ldg(xin + ((size_t)ta * B_ + b0 + b) * H_ + h);
                mt[b] = __ldg(mask + (size_t)(b0 + b) * T_ + ta);
            }
        }

        if (t > 0 && tid == 0) {
            unsigned target = (unsigned)t * 8u, v;
            do {
                asm volatile("ld.acquire.gpu.global.u32 %0, [%1];" : "=r"(v) : "l"(ctr) : "memory");
                if (v < target) __nanosleep(200);
            } while (v < target);
        }
        __syncthreads();

        if (t > 0) {
            const float4* src = (const float4*)&g_hex[dir * 2 + (t & 1)][0];
#pragma unroll
            for (int r = 0; r < 2; r++) {
                int idx = tid + r * 256;            // 512 float4 total
                int b = idx >> 7, jq = idx & 127;
                hs4[idx] = __ldcg(src + (size_t)(b0 + b) * 128 + jq);  // L2, not stale L1
            }
        }
        __syncthreads();

        ull acc[4] = {0ull, 0ull, 0ull, 0ull};
        if (t > 0) {
#pragma unroll
            for (int i = 0; i < 32; i++) {
                ulonglong2 w2 = wu[i];
#pragma unroll
                for (int b = 0; b < 4; b++) {
                    F4U2 q; q.f = hs4[b * 128 + kp * 32 + i];   // broadcast LDS.128
                    fma2(acc[b], q.u.x, w2.x);
                    fma2(acc[b], q.u.y, w2.y);
                }
            }
        }

        // split-K reduction across the 4 kp groups
        float racc[4];
#pragma unroll
        for (int b = 0; b < 4; b++) { float lo, hi; upk2(acc[b], lo, hi); racc[b] = lo + hi; }
        red[tid] = make_float4(racc[0], racc[1], racc[2], racc[3]);
        __syncthreads();
        if (tid < 128) {
            float4 o = red[tid + 128];
            red[tid] = make_float4(racc[0] + o.x, racc[1] + o.y, racc[2] + o.z, racc[3] + o.w);
        }
        __syncthreads();

        if (epi) {
            float4 a  = red[tid];
            float4 bb = red[tid + 64];
            float* hx = &g_hex[dir * 2 + ((t + 1) & 1)][0];
            float rec[4] = {a.x + bb.x, a.y + bb.y, a.z + bb.z, a.w + bb.w};
#pragma unroll
            for (int b = 0; b < 4; b++) {
                float hnew = tanhf(xv[b] + rec[b]);          // biases folded in xin
                float hcur = hnew * mt[b] + hprev[b] * (1.0f - mt[b]);
                hprev[b] = hcur;
                hx[(size_t)(b0 + b) * H_ + h] = hcur * nh[b];
                if (layer == 0)
                    g_seq[((size_t)ta * B_ + b0 + b) * 1024 + dir * 512 + h] = hcur;
                else
                    out[((size_t)(b0 + b) * T_ + ta) * 1024 + dir * 512 + h] = hcur;
            }
        }
        __syncthreads();   // epilogue writes complete before signaling

        if (tid == 0) {
            asm volatile("fence.acq_rel.gpu;" ::: "memory");
            asm volatile("red.relaxed.gpu.global.add.u32 [%0], 1;" :: "l"(ctr) : "memory");
        }
    }

    // final hidden states
    if (epi) {
#pragma unroll
        for (int b = 0; b < 4; b++)
            hn[((size_t)c * B_ + b0 + b) * H_ + h] = hprev[b];
    }
}

// ---------------------------------------------------------------------------
extern "C" void kernel_launch(void* const* d_in, const int* in_sizes, int n_in,
                              void* d_out, int out_size) {
    const float* x        = (const float*)d_in[0];
    const float* mask     = (const float*)d_in[1];
    const float* w_ih     = (const float*)d_in[2];
    const float* w_hh     = (const float*)d_in[3];
    const float* b_ih     = (const float*)d_in[4];
    const float* b_hh     = (const float*)d_in[5];
    const float* noise_in = (const float*)d_in[6];
    const float* noise_h  = (const float*)d_in[7];
    float* out = (float*)d_out;                       // [B,T,2H]
    float* hn  = out + (size_t)B_ * T_ * 2 * H_;      // [L*D,B,H]

    dim3 gg(H_ / 64, TB_ / 128, 2);                   // (8, 256, 2)

    init_kernel<<<1, 32>>>();
    gemm_kernel<<<gg, 256>>>(x, w_ih, b_ih, b_hh, noise_in, 0);
    recur_kernel<<<128, 256>>>(w_hh, noise_h, mask, out, hn, 0);
    gemm_kernel<<<gg, 256>>>(x, w_ih, b_ih, b_hh, noise_in, 1);
    recur_kernel<<<128, 256>>>(w_hh, noise_h, mask, out, hn, 1);
}

// round 7
// speedup vs baseline: 1.2602x; 1.2602x over previous
#include <cuda_runtime.h>
#include <math.h>

#define T_   1024
#define B_   32
#define IN_  1024
#define H_   512
#define TB_  (T_ * B_)

typedef unsigned long long ull;

// ---------------- static device scratch (no runtime alloc allowed) ----------
__device__ float g_xin[2][(size_t)TB_ * H_];   // per-direction input projections (biases folded)
__device__ float g_seq[(size_t)TB_ * 2 * H_];  // layer-0 output, [t][b][2H]

// ---------------- f32x2 helpers (ptxas never emits FFMA2 from C++) ----------
__device__ __forceinline__ ull pk2(float lo, float hi) {
    ull r; asm("mov.b64 %0, {%1,%2};" : "=l"(r) : "f"(lo), "f"(hi)); return r;
}
__device__ __forceinline__ void upk2(ull v, float& lo, float& hi) {
    asm("mov.b64 {%0,%1}, %2;" : "=f"(lo), "=f"(hi) : "l"(v));
}
__device__ __forceinline__ void fma2(ull& d, ull a, ull b) {
    asm("fma.rn.f32x2 %0, %1, %2, %0;" : "+l"(d) : "l"(a), "l"(b));
}
__device__ __forceinline__ unsigned smem_u32(const void* p) {
    unsigned a;
    asm("{ .reg .u64 t; cvta.to.shared.u64 t, %1; cvt.u32.u64 %0, t; }" : "=r"(a) : "l"(p));
    return a;
}
// DSMEM pull: map local smem addr to peer rank, 16B vector load
__device__ __forceinline__ float4 dsmem_ld(unsigned laddr, unsigned rank) {
    float4 v;
    asm volatile(
        "{\n\t.reg .u32 ra;\n\t"
        "mapa.shared::cluster.u32 ra, %4, %5;\n\t"
        "ld.shared::cluster.v4.f32 {%0,%1,%2,%3}, [ra];\n\t}"
        : "=f"(v.x), "=f"(v.y), "=f"(v.z), "=f"(v.w)
        : "r"(laddr), "r"(rank));
    return v;
}

// ---------------------------------------------------------------------------
// Input-projection GEMM (register-prefetch pipelined):
//   g_xin[cell][m][n] = sum_k A[m][k]*noise_in[c][b][k]*w_ih[c][n][k]
//                       + b_ih[c][n] + b_hh[c][n],   m = t*B + b
// Layer 0: A = x ([B,T,IN] batch-first). Layer 1: A = g_seq.
// Tile BM=128, BN=64, BK=16; 256 threads; 8m x 4n per thread via f32x2.
// ---------------------------------------------------------------------------
__global__ __launch_bounds__(256, 2) void gemm_kernel(
    const float* __restrict__ x,
    const float* __restrict__ w_ih,
    const float* __restrict__ b_ih,
    const float* __restrict__ b_hh,
    const float* __restrict__ noise_in,
    int layer)
{
    __shared__ float As[16 * 132];   // [k][m], padded
    __shared__ float Bs[16 * 68];    // [k][n], padded

    const int tid  = threadIdx.x;
    const int cell = blockIdx.z;
    const int cabs = layer * 2 + cell;
    const int n0   = blockIdx.x * 64;
    const int m0   = blockIdx.y * 128;
    const int tx   = tid & 15;
    const int ty   = tid >> 4;
    const int msub = ty * 8;
    const int nsub = tx * 4;

    const float* A  = (layer == 0) ? x : g_seq;
    const float* nz = noise_in + (size_t)cabs * B_ * IN_;
    const float* wb = w_ih + (size_t)cabs * H_ * IN_;
    float* outp = g_xin[cell];

    ull acc[4][4];
#pragma unroll
    for (int i = 0; i < 4; i++)
#pragma unroll
        for (int j = 0; j < 4; j++) acc[i][j] = 0ull;

    // A loader: 512 float4 per tile, 2 per thread
    const int e0 = tid, e1 = tid + 256;
    const int row0 = e0 >> 2, kq0 = (e0 & 3) * 4;
    const int row1 = e1 >> 2, kq1 = (e1 & 3) * 4;
    size_t ab0, ab1;
    if (layer == 0) {   // m = t*B + b ; x addr = b*(T*IN) + t*IN
        ab0 = (size_t)(row0 & 31) * ((size_t)T_ * IN_) + (size_t)(m0 / 32 + (row0 >> 5)) * IN_;
        ab1 = (size_t)(row1 & 31) * ((size_t)T_ * IN_) + (size_t)(m0 / 32 + (row1 >> 5)) * IN_;
    } else {
        ab0 = (size_t)(m0 + row0) * IN_;
        ab1 = (size_t)(m0 + row1) * IN_;
    }
    const size_t nb0 = (size_t)(row0 & 31) * IN_;
    const size_t nb1 = (size_t)(row1 & 31) * IN_;
    const int brow = tid >> 2, bkq = (tid & 3) * 4;
    const float* wrow = wb + (size_t)(n0 + brow) * IN_ + bkq;

    // prefetch registers for tile k0=0
    float4 xv0 = *(const float4*)(A + ab0 + kq0);
    float4 nv0 = *(const float4*)(nz + nb0 + kq0);
    float4 xv1 = *(const float4*)(A + ab1 + kq1);
    float4 nv1 = *(const float4*)(nz + nb1 + kq1);
    float4 wv0 = *(const float4*)(wrow);

    for (int k0 = 0; k0 < IN_; k0 += 16) {
        // stage current tile to smem
        As[(kq0 + 0) * 132 + row0] = xv0.x * nv0.x;
        As[(kq0 + 1) * 132 + row0] = xv0.y * nv0.y;
        As[(kq0 + 2) * 132 + row0] = xv0.z * nv0.z;
        As[(kq0 + 3) * 132 + row0] = xv0.w * nv0.w;
        As[(kq1 + 0) * 132 + row1] = xv1.x * nv1.x;
        As[(kq1 + 1) * 132 + row1] = xv1.y * nv1.y;
        As[(kq1 + 2) * 132 + row1] = xv1.z * nv1.z;
        As[(kq1 + 3) * 132 + row1] = xv1.w * nv1.w;
        Bs[(bkq + 0) * 68 + brow] = wv0.x;
        Bs[(bkq + 1) * 68 + brow] = wv0.y;
        Bs[(bkq + 2) * 68 + brow] = wv0.z;
        Bs[(bkq + 3) * 68 + brow] = wv0.w;
        __syncthreads();

        // issue next tile's global loads (overlap with compute below)
        const int kn = k0 + 16;
        if (kn < IN_) {
            xv0 = *(const float4*)(A + ab0 + kn + kq0);
            nv0 = *(const float4*)(nz + nb0 + kn + kq0);
            xv1 = *(const float4*)(A + ab1 + kn + kq1);
            nv1 = *(const float4*)(nz + nb1 + kn + kq1);
            wv0 = *(const float4*)(wrow + kn);
        }

#pragma unroll
        for (int k = 0; k < 16; k++) {
            float4 b4 = *(const float4*)&Bs[k * 68 + nsub];
            ull bd0 = pk2(b4.x, b4.x);
            ull bd1 = pk2(b4.y, b4.y);
            ull bd2 = pk2(b4.z, b4.z);
            ull bd3 = pk2(b4.w, b4.w);
#pragma unroll
            for (int mp = 0; mp < 4; mp++) {
                ull au = *(const ull*)&As[k * 132 + msub + 2 * mp];  // aligned m-pair
                fma2(acc[mp][0], au, bd0);
                fma2(acc[mp][1], au, bd1);
                fma2(acc[mp][2], au, bd2);
                fma2(acc[mp][3], au, bd3);
            }
        }
        __syncthreads();
    }

    // Epilogue: fold b_ih + b_hh, write xin
    float bi[4];
#pragma unroll
    for (int nn = 0; nn < 4; nn++) {
        int n = n0 + nsub + nn;
        bi[nn] = b_ih[cabs * H_ + n] + b_hh[cabs * H_ + n];
    }
#pragma unroll
    for (int mp = 0; mp < 4; mp++) {
        float lo[4], hi[4];
#pragma unroll
        for (int nn = 0; nn < 4; nn++) upk2(acc[mp][nn], lo[nn], hi[nn]);
        float4 v0 = make_float4(lo[0] + bi[0], lo[1] + bi[1], lo[2] + bi[2], lo[3] + bi[3]);
        float4 v1 = make_float4(hi[0] + bi[0], hi[1] + bi[1], hi[2] + bi[2], hi[3] + bi[3]);
        size_t r0 = (size_t)(m0 + msub + 2 * mp) * H_ + n0 + nsub;
        *(float4*)(outp + r0)      = v0;
        *(float4*)(outp + r0 + H_) = v1;
    }
}

// ---------------------------------------------------------------------------
// Recurrent scan, cluster version. 128 CTAs as 16 clusters of 8.
// Cluster = one (direction, batch-group); rank = h-slice (64 h-cols).
// h*noise_h exchanged via DSMEM: each CTA writes its slice to LOCAL smem
// (double buffered), posts mbarrier.arrive on all 8 peers (release@cluster),
// consumers acquire-wait on their local mbarrier and pull via mapa+ld.
// W_hh slice stays register-resident (f32x2 pairs).
// ---------------------------------------------------------------------------
__global__ __launch_bounds__(256, 1) __cluster_dims__(8, 1, 1)
void recur_kernel(
    const float* __restrict__ w_hh,
    const float* __restrict__ noise_h,
    const float* __restrict__ mask,
    float* __restrict__ out,      // d_out: [B,T,2H] (layer 1 writes here)
    float* __restrict__ hn,       // d_out + B*T*2H: [L*D,B,H]
    int layer)
{
    __shared__ float4 hs4[512];               // staged full h*nh: [b][jq]
    __shared__ float4 red[256];               // split-K reduction
    __shared__ float4 hbuf4[2][4][16];        // local slice, double buffered
    __shared__ alignas(8) unsigned long long mbar;

    const int tid  = threadIdx.x;
    const int bx   = blockIdx.x;
    const int dir  = bx >> 6;                 // 0 fwd, 1 bwd
    const int rank = bx & 7;                  // cluster rank == h-slice
    const int grp  = (bx >> 3) & 7;           // batch group
    const int b0   = grp * 4;
    const int h0   = rank * 64;
    const int kp   = tid >> 6;                // warp-uniform K partition
    const int hl   = tid & 63;
    const int h    = h0 + hl;
    const int c    = layer * 2 + dir;

    const unsigned mb_a   = smem_u32(&mbar);
    const unsigned hbuf_a = smem_u32(&hbuf4[0][0][0]);

    // init mbarrier (count 8: one arrive from each cluster CTA per step)
    if (tid == 0) {
        asm volatile("mbarrier.init.shared.b64 [%0], %1;" :: "r"(mb_a), "r"(8u) : "memory");
    }
    __syncthreads();
    asm volatile("barrier.cluster.arrive.aligned;" ::: "memory");
    asm volatile("barrier.cluster.wait.aligned;"   ::: "memory");

    // W_hh slice into registers as aligned f32x2 pairs: w[h][kp*128 .. +127]
    union F4U2 { float4 f; ulonglong2 u; };
    ulonglong2 wu[32];
    {
        const float4* wp = (const float4*)(w_hh + ((size_t)c * H_ + h) * H_ + kp * 128);
#pragma unroll
        for (int i = 0; i < 32; i++) { F4U2 t; t.f = wp[i]; wu[i] = t.u; }
    }

    const bool epi = (tid < 64);
    float nh[4], hprev[4];
    if (epi) {
#pragma unroll
        for (int b = 0; b < 4; b++) {
            nh[b]    = noise_h[((size_t)c * B_ + b0 + b) * H_ + h];
            hprev[b] = 0.0f;
        }
    }
    const float* xin = g_xin[dir];

    // pull indices: this thread grabs float4 idx = tid and tid+256 of [4][128]
    const int jqA = tid & 127,          bA = tid >> 7;       // b in {0,1}
    const int jqB = jqA,                bB = bA + 2;         // b in {2,3}
    const unsigned srcRank = (unsigned)(jqA >> 4);
    const unsigned offA = (unsigned)(bA * 16 + (jqA & 15)) * 16u;
    const unsigned offB = (unsigned)(bB * 16 + (jqB & 15)) * 16u;

    for (int t = 0; t < T_; t++) {
        const int ta = dir ? (T_ - 1 - t) : t;

        // prefetch xin + mask for this step (independent of the wait)
        float xv[4], mt[4];
        if (epi) {
#pragma unroll
            for (int b = 0; b < 4; b++) {
                xv[b] = __ldg(xin + ((size_t)ta * B_ + b0 + b) * H_ + h);
                mt[b] = __ldg(mask + (size_t)(b0 + b) * T_ + ta);
            }
        }

        if (t > 0) {
            // wait for arrival set t-1 (acquire @ cluster scope), all threads
            const unsigned parity = (unsigned)((t - 1) & 1);
            unsigned done;
            asm volatile(
                "{\n\t.reg .pred p;\n\t"
                "mbarrier.try_wait.parity.acquire.cluster.shared::cta.b64 p, [%1], %2;\n\t"
                "selp.b32 %0, 1, 0, p;\n\t}"
                : "=r"(done) : "r"(mb_a), "r"(parity) : "memory");
            if (!done) {
                asm volatile(
                    "{\n\t.reg .pred P1;\n\t"
                    "WL_%=:\n\t"
                    "mbarrier.try_wait.parity.acquire.cluster.shared::cta.b64 P1, [%0], %1, 0x989680;\n\t"
                    "@P1 bra.uni WD_%=;\n\t"
                    "bra.uni WL_%=;\n\t"
                    "WD_%=:\n\t}"
                    :: "r"(mb_a), "r"(parity) : "memory");
            }
            // pull full h*nh vector from the 8 cluster slices (buffer t&1)
            const unsigned bufo = (unsigned)(t & 1) * 1024u;
            float4 vA = dsmem_ld(hbuf_a + bufo + offA, srcRank);
            float4 vB = dsmem_ld(hbuf_a + bufo + offB, srcRank);
            hs4[bA * 128 + jqA] = vA;
            hs4[bB * 128 + jqB] = vB;
        }
        __syncthreads();

        ull acc[4] = {0ull, 0ull, 0ull, 0ull};
        if (t > 0) {
#pragma unroll
            for (int i = 0; i < 32; i++) {
                ulonglong2 w2 = wu[i];
#pragma unroll
                for (int b = 0; b < 4; b++) {
                    F4U2 q; q.f = hs4[b * 128 + kp * 32 + i];   // broadcast LDS.128
                    fma2(acc[b], q.u.x, w2.x);
                    fma2(acc[b], q.u.y, w2.y);
                }
            }
        }

        // single-sync split-K reduction across the 4 kp groups
        float racc[4];
#pragma unroll
        for (int b = 0; b < 4; b++) { float lo, hi; upk2(acc[b], lo, hi); racc[b] = lo + hi; }
        red[tid] = make_float4(racc[0], racc[1], racc[2], racc[3]);
        __syncthreads();

        if (epi) {
            float4 p0 = red[tid];
            float4 p1 = red[tid + 64];
            float4 p2 = red[tid + 128];
            float4 p3 = red[tid + 192];
            float rec[4] = { p0.x + p1.x + p2.x + p3.x,
                             p0.y + p1.y + p2.y + p3.y,
                             p0.z + p1.z + p2.z + p3.z,
                             p0.w + p1.w + p2.w + p3.w };
            float* hb = (float*)&hbuf4[(t + 1) & 1][0][0];
#pragma unroll
            for (int b = 0; b < 4; b++) {
                float hnew = tanhf(xv[b] + rec[b]);          // biases folded in xin
                float hcur = hnew * mt[b] + hprev[b] * (1.0f - mt[b]);
                hprev[b] = hcur;
                hb[b * 64 + hl] = hcur * nh[b];              // local smem slice
                if (layer == 0)
                    g_seq[((size_t)ta * B_ + b0 + b) * 1024 + dir * 512 + h] = hcur;
                else
                    out[((size_t)(b0 + b) * T_ + ta) * 1024 + dir * 512 + h] = hcur;
            }
        }
        __syncthreads();   // hbuf writes complete before publishing

        if (tid == 0) {
#pragma unroll
            for (unsigned r = 0; r < 8; r++) {
                asm volatile(
                    "{\n\t.reg .u32 ra;\n\t"
                    "mapa.shared::cluster.u32 ra, %0, %1;\n\t"
                    "mbarrier.arrive.shared::cluster.b64 _, [ra];\n\t}"
                    :: "r"(mb_a), "r"(r) : "memory");
            }
        }
    }

    // final hidden states
    if (epi) {
#pragma unroll
        for (int b = 0; b < 4; b++)
            hn[((size_t)c * B_ + b0 + b) * H_ + h] = hprev[b];
    }

    // no CTA may exit while peers can still arrive on its smem barrier
    asm volatile("barrier.cluster.arrive.aligned;" ::: "memory");
    asm volatile("barrier.cluster.wait.aligned;"   ::: "memory");
}

// ---------------------------------------------------------------------------
extern "C" void kernel_launch(void* const* d_in, const int* in_sizes, int n_in,
                              void* d_out, int out_size) {
    const float* x        = (const float*)d_in[0];
    const float* mask     = (const float*)d_in[1];
    const float* w_ih     = (const float*)d_in[2];
    const float* w_hh     = (const float*)d_in[3];
    const float* b_ih     = (const float*)d_in[4];
    const float* b_hh     = (const float*)d_in[5];
    const float* noise_in = (const float*)d_in[6];
    const float* noise_h  = (const float*)d_in[7];
    float* out = (float*)d_out;                       // [B,T,2H]
    float* hn  = out + (size_t)B_ * T_ * 2 * H_;      // [L*D,B,H]

    dim3 gg(H_ / 64, TB_ / 128, 2);                   // (8, 256, 2)

    gemm_kernel<<<gg, 256>>>(x, w_ih, b_ih, b_hh, noise_in, 0);
    recur_kernel<<<128, 256>>>(w_hh, noise_h, mask, out, hn, 0);
    gemm_kernel<<<gg, 256>>>(x, w_ih, b_ih, b_hh, noise_in, 1);
    recur_kernel<<<128, 256>>>(w_hh, noise_h, mask, out, hn, 1);
}

// round 8
// speedup vs baseline: 1.2898x; 1.0235x over previous
#include <cuda_runtime.h>
#include <math.h>

#define T_   1024
#define B_   32
#define IN_  1024
#define H_   512
#define TB_  (T_ * B_)

typedef unsigned long long ull;

// ---------------- static device scratch (no runtime alloc allowed) ----------
__device__ float g_xin[2][(size_t)TB_ * H_];   // per-direction input projections (biases folded)
__device__ float g_seq[(size_t)TB_ * 2 * H_];  // layer-0 output, [t][b][2H]

// ---------------- f32x2 helpers (ptxas never emits FFMA2 from C++) ----------
__device__ __forceinline__ ull pk2(float lo, float hi) {
    ull r; asm("mov.b64 %0, {%1,%2};" : "=l"(r) : "f"(lo), "f"(hi)); return r;
}
__device__ __forceinline__ void upk2(ull v, float& lo, float& hi) {
    asm("mov.b64 {%0,%1}, %2;" : "=f"(lo), "=f"(hi) : "l"(v));
}
__device__ __forceinline__ void fma2(ull& d, ull a, ull b) {
    asm("fma.rn.f32x2 %0, %1, %2, %0;" : "+l"(d) : "l"(a), "l"(b));
}
__device__ __forceinline__ unsigned smem_u32(const void* p) {
    unsigned a;
    asm("{ .reg .u64 t; cvta.to.shared.u64 t, %1; cvt.u32.u64 %0, t; }" : "=r"(a) : "l"(p));
    return a;
}
// DSMEM push: map local smem addr to peer rank, scalar store
__device__ __forceinline__ void dsmem_st(unsigned laddr, unsigned rank, float v) {
    asm volatile(
        "{\n\t.reg .u32 ra;\n\t"
        "mapa.shared::cluster.u32 ra, %0, %1;\n\t"
        "st.shared::cluster.f32 [ra], %2;\n\t}"
        :: "r"(laddr), "r"(rank), "f"(v) : "memory");
}

// ---------------------------------------------------------------------------
// Input-projection GEMM (register-prefetch pipelined) — unchanged from R7.
//   g_xin[cell][m][n] = sum_k A[m][k]*noise_in[c][b][k]*w_ih[c][n][k]
//                       + b_ih[c][n] + b_hh[c][n],   m = t*B + b
// ---------------------------------------------------------------------------
__global__ __launch_bounds__(256, 2) void gemm_kernel(
    const float* __restrict__ x,
    const float* __restrict__ w_ih,
    const float* __restrict__ b_ih,
    const float* __restrict__ b_hh,
    const float* __restrict__ noise_in,
    int layer)
{
    __shared__ float As[16 * 132];   // [k][m], padded
    __shared__ float Bs[16 * 68];    // [k][n], padded

    const int tid  = threadIdx.x;
    const int cell = blockIdx.z;
    const int cabs = layer * 2 + cell;
    const int n0   = blockIdx.x * 64;
    const int m0   = blockIdx.y * 128;
    const int tx   = tid & 15;
    const int ty   = tid >> 4;
    const int msub = ty * 8;
    const int nsub = tx * 4;

    const float* A  = (layer == 0) ? x : g_seq;
    const float* nz = noise_in + (size_t)cabs * B_ * IN_;
    const float* wb = w_ih + (size_t)cabs * H_ * IN_;
    float* outp = g_xin[cell];

    ull acc[4][4];
#pragma unroll
    for (int i = 0; i < 4; i++)
#pragma unroll
        for (int j = 0; j < 4; j++) acc[i][j] = 0ull;

    const int e0 = tid, e1 = tid + 256;
    const int row0 = e0 >> 2, kq0 = (e0 & 3) * 4;
    const int row1 = e1 >> 2, kq1 = (e1 & 3) * 4;
    size_t ab0, ab1;
    if (layer == 0) {   // m = t*B + b ; x addr = b*(T*IN) + t*IN
        ab0 = (size_t)(row0 & 31) * ((size_t)T_ * IN_) + (size_t)(m0 / 32 + (row0 >> 5)) * IN_;
        ab1 = (size_t)(row1 & 31) * ((size_t)T_ * IN_) + (size_t)(m0 / 32 + (row1 >> 5)) * IN_;
    } else {
        ab0 = (size_t)(m0 + row0) * IN_;
        ab1 = (size_t)(m0 + row1) * IN_;
    }
    const size_t nb0 = (size_t)(row0 & 31) * IN_;
    const size_t nb1 = (size_t)(row1 & 31) * IN_;
    const int brow = tid >> 2, bkq = (tid & 3) * 4;
    const float* wrow = wb + (size_t)(n0 + brow) * IN_ + bkq;

    float4 xv0 = *(const float4*)(A + ab0 + kq0);
    float4 nv0 = *(const float4*)(nz + nb0 + kq0);
    float4 xv1 = *(const float4*)(A + ab1 + kq1);
    float4 nv1 = *(const float4*)(nz + nb1 + kq1);
    float4 wv0 = *(const float4*)(wrow);

    for (int k0 = 0; k0 < IN_; k0 += 16) {
        As[(kq0 + 0) * 132 + row0] = xv0.x * nv0.x;
        As[(kq0 + 1) * 132 + row0] = xv0.y * nv0.y;
        As[(kq0 + 2) * 132 + row0] = xv0.z * nv0.z;
        As[(kq0 + 3) * 132 + row0] = xv0.w * nv0.w;
        As[(kq1 + 0) * 132 + row1] = xv1.x * nv1.x;
        As[(kq1 + 1) * 132 + row1] = xv1.y * nv1.y;
        As[(kq1 + 2) * 132 + row1] = xv1.z * nv1.z;
        As[(kq1 + 3) * 132 + row1] = xv1.w * nv1.w;
        Bs[(bkq + 0) * 68 + brow] = wv0.x;
        Bs[(bkq + 1) * 68 + brow] = wv0.y;
        Bs[(bkq + 2) * 68 + brow] = wv0.z;
        Bs[(bkq + 3) * 68 + brow] = wv0.w;
        __syncthreads();

        const int kn = k0 + 16;
        if (kn < IN_) {
            xv0 = *(const float4*)(A + ab0 + kn + kq0);
            nv0 = *(const float4*)(nz + nb0 + kn + kq0);
            xv1 = *(const float4*)(A + ab1 + kn + kq1);
            nv1 = *(const float4*)(nz + nb1 + kn + kq1);
            wv0 = *(const float4*)(wrow + kn);
        }

#pragma unroll
        for (int k = 0; k < 16; k++) {
            float4 b4 = *(const float4*)&Bs[k * 68 + nsub];
            ull bd0 = pk2(b4.x, b4.x);
            ull bd1 = pk2(b4.y, b4.y);
            ull bd2 = pk2(b4.z, b4.z);
            ull bd3 = pk2(b4.w, b4.w);
#pragma unroll
            for (int mp = 0; mp < 4; mp++) {
                ull au = *(const ull*)&As[k * 132 + msub + 2 * mp];
                fma2(acc[mp][0], au, bd0);
                fma2(acc[mp][1], au, bd1);
                fma2(acc[mp][2], au, bd2);
                fma2(acc[mp][3], au, bd3);
            }
        }
        __syncthreads();
    }

    float bi[4];
#pragma unroll
    for (int nn = 0; nn < 4; nn++) {
        int n = n0 + nsub + nn;
        bi[nn] = b_ih[cabs * H_ + n] + b_hh[cabs * H_ + n];
    }
#pragma unroll
    for (int mp = 0; mp < 4; mp++) {
        float lo[4], hi[4];
#pragma unroll
        for (int nn = 0; nn < 4; nn++) upk2(acc[mp][nn], lo[nn], hi[nn]);
        float4 v0 = make_float4(lo[0] + bi[0], lo[1] + bi[1], lo[2] + bi[2], lo[3] + bi[3]);
        float4 v1 = make_float4(hi[0] + bi[0], hi[1] + bi[1], hi[2] + bi[2], hi[3] + bi[3]);
        size_t r0 = (size_t)(m0 + msub + 2 * mp) * H_ + n0 + nsub;
        *(float4*)(outp + r0)      = v0;
        *(float4*)(outp + r0 + H_) = v1;
    }
}

// ---------------------------------------------------------------------------
// Recurrent scan v2: PUSH exchange. 16 clusters of 8 CTAs.
// Each CTA: 4 batches x 64 h-cols, W_hh slice register-resident.
// Epilogue thread (kp,hl) owns output (b=kp, h=h0+hl): it computes tanh,
// pushes h*nh into all 8 peers' local double-buffered hbuf via
// mapa+st.shared::cluster, then tid0 fences (cluster) and posts 8 arrives.
// Consumers wake on local mbarrier and read hbuf LOCALLY in the fma loop.
// ---------------------------------------------------------------------------
__global__ __launch_bounds__(256, 1) __cluster_dims__(8, 1, 1)
void recur_kernel(
    const float* __restrict__ w_hh,
    const float* __restrict__ noise_h,
    const float* __restrict__ mask,
    float* __restrict__ out,      // d_out: [B,T,2H] (layer 1 writes here)
    float* __restrict__ hn,       // d_out + B*T*2H: [L*D,B,H]
    int layer)
{
    __shared__ float hbuf[2][4 * 512];        // full h*nh vector, double buffered (16KB)
    __shared__ float red2[4][4][64];          // [kp][b][hl] partials (4KB)
    __shared__ alignas(8) unsigned long long mbar;

    const int tid  = threadIdx.x;
    const int bx   = blockIdx.x;
    const int dir  = bx >> 6;                 // 0 fwd, 1 bwd
    const int rank = bx & 7;                  // cluster rank == h-slice
    const int grp  = (bx >> 3) & 7;           // batch group
    const int b0   = grp * 4;
    const int h0   = rank * 64;
    const int kp   = tid >> 6;                // K partition AND owned batch b
    const int hl   = tid & 63;
    const int h    = h0 + hl;
    const int c    = layer * 2 + dir;

    const unsigned mb_a = smem_u32(&mbar);
    const unsigned hb_a = smem_u32(&hbuf[0][0]);

    if (tid == 0) {
        asm volatile("mbarrier.init.shared.b64 [%0], %1;" :: "r"(mb_a), "r"(8u) : "memory");
    }
    __syncthreads();
    asm volatile("barrier.cluster.arrive.aligned;" ::: "memory");
    asm volatile("barrier.cluster.wait.aligned;"   ::: "memory");

    // W_hh slice into registers as aligned f32x2 pairs: w[h][kp*128 .. +127]
    union F4U2 { float4 f; ulonglong2 u; };
    ulonglong2 wu[32];
    {
        const float4* wp = (const float4*)(w_hh + ((size_t)c * H_ + h) * H_ + kp * 128);
#pragma unroll
        for (int i = 0; i < 32; i++) { F4U2 t; t.f = wp[i]; wu[i] = t.u; }
    }

    // per-thread recurrent state for output (b=kp, h)
    const float nh = noise_h[((size_t)c * B_ + b0 + kp) * H_ + h];
    float hprev = 0.0f;
    const float* xin = g_xin[dir];
    // push offset of OUR value inside the full vector: (b*512 + h)*4 bytes
    const unsigned my_off = (unsigned)(kp * 512 + h) * 4u;

    for (int t = 0; t < T_; t++) {
        const int ta = dir ? (T_ - 1 - t) : t;

        // prefetch xin + mask for this step (independent of the wait)
        const float xv = __ldg(xin + ((size_t)ta * B_ + b0 + kp) * H_ + h);
        const float mt = __ldg(mask + (size_t)(b0 + kp) * T_ + ta);

        if (t > 0) {
            const unsigned parity = (unsigned)((t - 1) & 1);
            unsigned done;
            asm volatile(
                "{\n\t.reg .pred p;\n\t"
                "mbarrier.try_wait.parity.acquire.cluster.shared::cta.b64 p, [%1], %2;\n\t"
                "selp.b32 %0, 1, 0, p;\n\t}"
                : "=r"(done) : "r"(mb_a), "r"(parity) : "memory");
            if (!done) {
                asm volatile(
                    "{\n\t.reg .pred P1;\n\t"
                    "WL_%=:\n\t"
                    "mbarrier.try_wait.parity.acquire.cluster.shared::cta.b64 P1, [%0], %1, 0x989680;\n\t"
                    "@P1 bra.uni WD_%=;\n\t"
                    "bra.uni WL_%=;\n\t"
                    "WD_%=:\n\t}"
                    :: "r"(mb_a), "r"(parity) : "memory");
            }
        }

        // dot products over our K slice, reading LOCAL hbuf (broadcast LDS.128)
        ull acc[4] = {0ull, 0ull, 0ull, 0ull};
        if (t > 0) {
            const float4* hb = (const float4*)&hbuf[t & 1][0];
#pragma unroll
            for (int i = 0; i < 32; i++) {
                ulonglong2 w2 = wu[i];
#pragma unroll
                for (int b = 0; b < 4; b++) {
                    F4U2 q; q.f = hb[b * 128 + kp * 32 + i];
                    fma2(acc[b], q.u.x, w2.x);
                    fma2(acc[b], q.u.y, w2.y);
                }
            }
        }
#pragma unroll
        for (int b = 0; b < 4; b++) {
            float lo, hi; upk2(acc[b], lo, hi);
            red2[kp][b][hl] = lo + hi;
        }
        __syncthreads();

        // epilogue: every thread finishes ONE output (b=kp, h)
        {
            const float rec = red2[0][kp][hl] + red2[1][kp][hl]
                            + red2[2][kp][hl] + red2[3][kp][hl];
            const float hnew = tanhf(xv + rec);               // biases folded in xin
            const float hcur = hnew * mt + hprev * (1.0f - mt);
            hprev = hcur;
            const float v = hcur * nh;
            const unsigned dst = hb_a + (unsigned)(((t + 1) & 1) * 8192) + my_off;
#pragma unroll
            for (unsigned r = 0; r < 8; r++) dsmem_st(dst, r, v);
            if (layer == 0)
                g_seq[((size_t)ta * B_ + b0 + kp) * 1024 + dir * 512 + h] = hcur;
            else
                out[((size_t)(b0 + kp) * T_ + ta) * 1024 + dir * 512 + h] = hcur;
        }
        __syncthreads();   // all pushes issued before publishing

        if (tid == 0) {
            asm volatile("fence.acq_rel.cluster;" ::: "memory");
#pragma unroll
            for (unsigned r = 0; r < 8; r++) {
                asm volatile(
                    "{\n\t.reg .u32 ra;\n\t"
                    "mapa.shared::cluster.u32 ra, %0, %1;\n\t"
                    "mbarrier.arrive.shared::cluster.b64 _, [ra];\n\t}"
                    :: "r"(mb_a), "r"(r) : "memory");
            }
        }
    }

    // final hidden states
    hn[((size_t)c * B_ + b0 + kp) * H_ + h] = hprev;

    // no CTA may exit while peers can still arrive/store into its smem
    asm volatile("barrier.cluster.arrive.aligned;" ::: "memory");
    asm volatile("barrier.cluster.wait.aligned;"   ::: "memory");
}

// ---------------------------------------------------------------------------
extern "C" void kernel_launch(void* const* d_in, const int* in_sizes, int n_in,
                              void* d_out, int out_size) {
    const float* x        = (const float*)d_in[0];
    const float* mask     = (const float*)d_in[1];
    const float* w_ih     = (const float*)d_in[2];
    const float* w_hh     = (const float*)d_in[3];
    const float* b_ih     = (const float*)d_in[4];
    const float* b_hh     = (const float*)d_in[5];
    const float* noise_in = (const float*)d_in[6];
    const float* noise_h  = (const float*)d_in[7];
    float* out = (float*)d_out;                       // [B,T,2H]
    float* hn  = out + (size_t)B_ * T_ * 2 * H_;      // [L*D,B,H]

    dim3 gg(H_ / 64, TB_ / 128, 2);                   // (8, 256, 2)

    gemm_kernel<<<gg, 256>>>(x, w_ih, b_ih, b_hh, noise_in, 0);
    recur_kernel<<<128, 256>>>(w_hh, noise_h, mask, out, hn, 0);
    gemm_kernel<<<gg, 256>>>(x, w_ih, b_ih, b_hh, noise_in, 1);
    recur_kernel<<<128, 256>>>(w_hh, noise_h, mask, out, hn, 1);
}

// round 9
// speedup vs baseline: 1.2898x; 1.0001x over previous
#include <cuda_runtime.h>
#include <math.h>

#define T_   1024
#define B_   32
#define IN_  1024
#define H_   512
#define TB_  (T_ * B_)

typedef unsigned long long ull;

// ---------------- static device scratch (no runtime alloc allowed) ----------
__device__ float g_xin[2][(size_t)TB_ * H_];   // per-direction input projections (biases folded)
__device__ float g_seq[(size_t)TB_ * 2 * H_];  // layer-0 output, [t][b][2H]

// ---------------- f32x2 helpers (ptxas never emits FFMA2 from C++) ----------
__device__ __forceinline__ ull pk2(float lo, float hi) {
    ull r; asm("mov.b64 %0, {%1,%2};" : "=l"(r) : "f"(lo), "f"(hi)); return r;
}
__device__ __forceinline__ void upk2(ull v, float& lo, float& hi) {
    asm("mov.b64 {%0,%1}, %2;" : "=f"(lo), "=f"(hi) : "l"(v));
}
__device__ __forceinline__ void fma2(ull& d, ull a, ull b) {
    asm("fma.rn.f32x2 %0, %1, %2, %0;" : "+l"(d) : "l"(a), "l"(b));
}
__device__ __forceinline__ unsigned smem_u32(const void* p) {
    unsigned a;
    asm("{ .reg .u64 t; cvta.to.shared.u64 t, %1; cvt.u32.u64 %0, t; }" : "=r"(a) : "l"(p));
    return a;
}
// DSMEM push: map local smem addr to peer rank, scalar store
__device__ __forceinline__ void dsmem_st(unsigned laddr, unsigned rank, float v) {
    asm volatile(
        "{\n\t.reg .u32 ra;\n\t"
        "mapa.shared::cluster.u32 ra, %0, %1;\n\t"
        "st.shared::cluster.f32 [ra], %2;\n\t}"
        :: "r"(laddr), "r"(rank), "f"(v) : "memory");
}

// ---------------------------------------------------------------------------
// Input-projection GEMM (register-prefetch pipelined) — unchanged from R8.
//   g_xin[cell][m][n] = sum_k A[m][k]*noise_in[c][b][k]*w_ih[c][n][k]
//                       + b_ih[c][n] + b_hh[c][n],   m = t*B + b
// ---------------------------------------------------------------------------
__global__ __launch_bounds__(256, 2) void gemm_kernel(
    const float* __restrict__ x,
    const float* __restrict__ w_ih,
    const float* __restrict__ b_ih,
    const float* __restrict__ b_hh,
    const float* __restrict__ noise_in,
    int layer)
{
    __shared__ float As[16 * 132];   // [k][m], padded
    __shared__ float Bs[16 * 68];    // [k][n], padded

    const int tid  = threadIdx.x;
    const int cell = blockIdx.z;
    const int cabs = layer * 2 + cell;
    const int n0   = blockIdx.x * 64;
    const int m0   = blockIdx.y * 128;
    const int tx   = tid & 15;
    const int ty   = tid >> 4;
    const int msub = ty * 8;
    const int nsub = tx * 4;

    const float* A  = (layer == 0) ? x : g_seq;
    const float* nz = noise_in + (size_t)cabs * B_ * IN_;
    const float* wb = w_ih + (size_t)cabs * H_ * IN_;
    float* outp = g_xin[cell];

    ull acc[4][4];
#pragma unroll
    for (int i = 0; i < 4; i++)
#pragma unroll
        for (int j = 0; j < 4; j++) acc[i][j] = 0ull;

    const int e0 = tid, e1 = tid + 256;
    const int row0 = e0 >> 2, kq0 = (e0 & 3) * 4;
    const int row1 = e1 >> 2, kq1 = (e1 & 3) * 4;
    size_t ab0, ab1;
    if (layer == 0) {   // m = t*B + b ; x addr = b*(T*IN) + t*IN
        ab0 = (size_t)(row0 & 31) * ((size_t)T_ * IN_) + (size_t)(m0 / 32 + (row0 >> 5)) * IN_;
        ab1 = (size_t)(row1 & 31) * ((size_t)T_ * IN_) + (size_t)(m0 / 32 + (row1 >> 5)) * IN_;
    } else {
        ab0 = (size_t)(m0 + row0) * IN_;
        ab1 = (size_t)(m0 + row1) * IN_;
    }
    const size_t nb0 = (size_t)(row0 & 31) * IN_;
    const size_t nb1 = (size_t)(row1 & 31) * IN_;
    const int brow = tid >> 2, bkq = (tid & 3) * 4;
    const float* wrow = wb + (size_t)(n0 + brow) * IN_ + bkq;

    float4 xv0 = *(const float4*)(A + ab0 + kq0);
    float4 nv0 = *(const float4*)(nz + nb0 + kq0);
    float4 xv1 = *(const float4*)(A + ab1 + kq1);
    float4 nv1 = *(const float4*)(nz + nb1 + kq1);
    float4 wv0 = *(const float4*)(wrow);

    for (int k0 = 0; k0 < IN_; k0 += 16) {
        As[(kq0 + 0) * 132 + row0] = xv0.x * nv0.x;
        As[(kq0 + 1) * 132 + row0] = xv0.y * nv0.y;
        As[(kq0 + 2) * 132 + row0] = xv0.z * nv0.z;
        As[(kq0 + 3) * 132 + row0] = xv0.w * nv0.w;
        As[(kq1 + 0) * 132 + row1] = xv1.x * nv1.x;
        As[(kq1 + 1) * 132 + row1] = xv1.y * nv1.y;
        As[(kq1 + 2) * 132 + row1] = xv1.z * nv1.z;
        As[(kq1 + 3) * 132 + row1] = xv1.w * nv1.w;
        Bs[(bkq + 0) * 68 + brow] = wv0.x;
        Bs[(bkq + 1) * 68 + brow] = wv0.y;
        Bs[(bkq + 2) * 68 + brow] = wv0.z;
        Bs[(bkq + 3) * 68 + brow] = wv0.w;
        __syncthreads();

        const int kn = k0 + 16;
        if (kn < IN_) {
            xv0 = *(const float4*)(A + ab0 + kn + kq0);
            nv0 = *(const float4*)(nz + nb0 + kn + kq0);
            xv1 = *(const float4*)(A + ab1 + kn + kq1);
            nv1 = *(const float4*)(nz + nb1 + kn + kq1);
            wv0 = *(const float4*)(wrow + kn);
        }

#pragma unroll
        for (int k = 0; k < 16; k++) {
            float4 b4 = *(const float4*)&Bs[k * 68 + nsub];
            ull bd0 = pk2(b4.x, b4.x);
            ull bd1 = pk2(b4.y, b4.y);
            ull bd2 = pk2(b4.z, b4.z);
            ull bd3 = pk2(b4.w, b4.w);
#pragma unroll
            for (int mp = 0; mp < 4; mp++) {
                ull au = *(const ull*)&As[k * 132 + msub + 2 * mp];
                fma2(acc[mp][0], au, bd0);
                fma2(acc[mp][1], au, bd1);
                fma2(acc[mp][2], au, bd2);
                fma2(acc[mp][3], au, bd3);
            }
        }
        __syncthreads();
    }

    float bi[4];
#pragma unroll
    for (int nn = 0; nn < 4; nn++) {
        int n = n0 + nsub + nn;
        bi[nn] = b_ih[cabs * H_ + n] + b_hh[cabs * H_ + n];
    }
#pragma unroll
    for (int mp = 0; mp < 4; mp++) {
        float lo[4], hi[4];
#pragma unroll
        for (int nn = 0; nn < 4; nn++) upk2(acc[mp][nn], lo[nn], hi[nn]);
        float4 v0 = make_float4(lo[0] + bi[0], lo[1] + bi[1], lo[2] + bi[2], lo[3] + bi[3]);
        float4 v1 = make_float4(hi[0] + bi[0], hi[1] + bi[1], hi[2] + bi[2], hi[3] + bi[3]);
        size_t r0 = (size_t)(m0 + msub + 2 * mp) * H_ + n0 + nsub;
        *(float4*)(outp + r0)      = v0;
        *(float4*)(outp + r0 + H_) = v1;
    }
}

// ---------------------------------------------------------------------------
// Recurrent scan v3: one hardware cluster barrier per step, NO mbarriers,
// NO fences. 16 clusters of 8 CTAs. Each CTA: 4 batches x 64 h-cols,
// W_hh slice register-resident. Thread (kp,hl) owns output (b=kp, h=h0+hl):
// computes tanh, writes its value into the LOCAL double-buffered hbuf and
// pushes it to the 7 peers (st.shared::cluster). barrier.cluster.arrive
// (release, orders the remote stores) then .wait gates the next step.
// Double buffer + full per-step barrier => no read/write races possible.
// ---------------------------------------------------------------------------
__global__ __launch_bounds__(256, 1) __cluster_dims__(8, 1, 1)
void recur_kernel(
    const float* __restrict__ w_hh,
    const float* __restrict__ noise_h,
    const float* __restrict__ mask,
    float* __restrict__ out,      // d_out: [B,T,2H] (layer 1 writes here)
    float* __restrict__ hn,       // d_out + B*T*2H: [L*D,B,H]
    int layer)
{
    __shared__ float hbuf[2][4 * 512];        // full h*nh vector, double buffered (16KB)
    __shared__ float red2[4][4][64];          // [kp][b][hl] partials (4KB)

    const int tid  = threadIdx.x;
    const int bx   = blockIdx.x;
    const int dir  = bx >> 6;                 // 0 fwd, 1 bwd
    const int rank = bx & 7;                  // cluster rank == h-slice
    const int grp  = (bx >> 3) & 7;           // batch group
    const int b0   = grp * 4;
    const int h0   = rank * 64;
    const int kp   = tid >> 6;                // K partition AND owned batch b
    const int hl   = tid & 63;
    const int h    = h0 + hl;
    const int c    = layer * 2 + dir;

    const unsigned hb_a = smem_u32(&hbuf[0][0]);

    // W_hh slice into registers as aligned f32x2 pairs: w[h][kp*128 .. +127]
    union F4U2 { float4 f; ulonglong2 u; };
    ulonglong2 wu[32];
    {
        const float4* wp = (const float4*)(w_hh + ((size_t)c * H_ + h) * H_ + kp * 128);
#pragma unroll
        for (int i = 0; i < 32; i++) { F4U2 t; t.f = wp[i]; wu[i] = t.u; }
    }

    // per-thread recurrent state for output (b=kp, h)
    const float nh = noise_h[((size_t)c * B_ + b0 + kp) * H_ + h];
    float hprev = 0.0f;
    const float* xin = g_xin[dir];
    // byte offset of OUR value inside the full vector: (b*512 + h)*4
    const unsigned my_off = (unsigned)(kp * 512 + h) * 4u;

    for (int t = 0; t < T_; t++) {
        const int ta = dir ? (T_ - 1 - t) : t;

        // prefetch xin + mask for this step (off the critical path)
        const float xv = __ldg(xin + ((size_t)ta * B_ + b0 + kp) * H_ + h);
        const float mt = __ldg(mask + (size_t)(b0 + kp) * T_ + ta);

        // dot products over our K slice, reading LOCAL hbuf (broadcast LDS.128)
        ull acc[4] = {0ull, 0ull, 0ull, 0ull};
        if (t > 0) {
            const float4* hb = (const float4*)&hbuf[t & 1][0];
#pragma unroll
            for (int i = 0; i < 32; i++) {
                ulonglong2 w2 = wu[i];
#pragma unroll
                for (int b = 0; b < 4; b++) {
                    F4U2 q; q.f = hb[b * 128 + kp * 32 + i];
                    fma2(acc[b], q.u.x, w2.x);
                    fma2(acc[b], q.u.y, w2.y);
                }
            }
        }
#pragma unroll
        for (int b = 0; b < 4; b++) {
            float lo, hi; upk2(acc[b], lo, hi);
            red2[kp][b][hl] = lo + hi;
        }
        __syncthreads();

        // epilogue: every thread finishes ONE output (b=kp, h)
        {
            const float rec = red2[0][kp][hl] + red2[1][kp][hl]
                            + red2[2][kp][hl] + red2[3][kp][hl];
            const float hnew = tanhf(xv + rec);               // biases folded in xin
            const float hcur = hnew * mt + hprev * (1.0f - mt);
            hprev = hcur;
            const float v = hcur * nh;
            const int nb = (t + 1) & 1;
            hbuf[nb][kp * 512 + h] = v;                       // own slice, local store
            const unsigned dst = hb_a + (unsigned)(nb * 8192) + my_off;
#pragma unroll
            for (unsigned r = 0; r < 8; r++)
                if (r != (unsigned)rank) dsmem_st(dst, r, v); // 7 remote pushes
            if (layer == 0)
                g_seq[((size_t)ta * B_ + b0 + kp) * 1024 + dir * 512 + h] = hcur;
            else
                out[((size_t)(b0 + kp) * T_ + ta) * 1024 + dir * 512 + h] = hcur;
        }

        // one hardware cluster barrier per step: orders all remote stores
        // (release) and gates every CTA's next step (acquire).
        asm volatile("barrier.cluster.arrive.aligned;" ::: "memory");
        asm volatile("barrier.cluster.wait.aligned;"   ::: "memory");
    }

    // final hidden states (after last barrier: no more remote traffic)
    hn[((size_t)c * B_ + b0 + kp) * H_ + h] = hprev;
}

// ---------------------------------------------------------------------------
extern "C" void kernel_launch(void* const* d_in, const int* in_sizes, int n_in,
                              void* d_out, int out_size) {
    const float* x        = (const float*)d_in[0];
    const float* mask     = (const float*)d_in[1];
    const float* w_ih     = (const float*)d_in[2];
    const float* w_hh     = (const float*)d_in[3];
    const float* b_ih     = (const float*)d_in[4];
    const float* b_hh     = (const float*)d_in[5];
    const float* noise_in = (const float*)d_in[6];
    const float* noise_h  = (const float*)d_in[7];
    float* out = (float*)d_out;                       // [B,T,2H]
    float* hn  = out + (size_t)B_ * T_ * 2 * H_;      // [L*D,B,H]

    dim3 gg(H_ / 64, TB_ / 128, 2);                   // (8, 256, 2)

    gemm_kernel<<<gg, 256>>>(x, w_ih, b_ih, b_hh, noise_in, 0);
    recur_kernel<<<128, 256>>>(w_hh, noise_h, mask, out, hn, 0);
    gemm_kernel<<<gg, 256>>>(x, w_ih, b_ih, b_hh, noise_in, 1);
    recur_kernel<<<128, 256>>>(w_hh, noise_h, mask, out, hn, 1);
}